// round 6
// baseline (speedup 1.0000x reference)
#include <cuda_runtime.h>
#include <cstdint>

#define N_NODES 4096
#define IN_FEAT 512
#define E3      1536
#define HEADS   8
#define HEAD_DIM 64
#define BAND    0.075f

// ---------------- scratch (static device globals: no allocation) ------------
__device__ float    g_xT[IN_FEAT * N_NODES];     // [k][m]
__device__ float    g_WT[IN_FEAT * E3];          // [k][n]
__device__ float    g_Qh[HEADS * N_NODES * 64];  // head-major [h][node][d]
__device__ float    g_Kh[HEADS * N_NODES * 64];
__device__ float    g_Kp[HEADS * 64 * 4096];     // per-(h,tile) permuted tf32 B images
__device__ float    g_V[N_NODES * 512];          // node-major
__device__ unsigned g_adjbits[128 * N_NODES];    // [word][q]
__device__ int      g_argmax[HEADS * N_NODES];
__device__ int      g_fixcount;
__device__ int      g_fixlist[HEADS * N_NODES];

// ---------------- packed fp32x2 helpers (qkv gemm) ---------------------------
__device__ __forceinline__ unsigned long long pack2(float lo, float hi) {
    unsigned long long r;
    asm("mov.b64 %0, {%1, %2};" : "=l"(r) : "f"(lo), "f"(hi));
    return r;
}
__device__ __forceinline__ void unpack2(unsigned long long v, float& lo, float& hi) {
    asm("mov.b64 {%0, %1}, %2;" : "=f"(lo), "=f"(hi) : "l"(v));
}
__device__ __forceinline__ unsigned long long fma2(unsigned long long a,
                                                   unsigned long long b,
                                                   unsigned long long c) {
    unsigned long long d;
    asm("fma.rn.f32x2 %0, %1, %2, %3;" : "=l"(d) : "l"(a), "l"(b), "l"(c));
    return d;
}

// ---------------- mbarrier + bulk-copy helpers --------------------------------
__device__ __forceinline__ uint32_t smem_u32(const void* p) {
    uint32_t a;
    asm("{ .reg .u64 t; cvta.to.shared.u64 t, %1; cvt.u32.u64 %0, t; }"
        : "=r"(a) : "l"(p));
    return a;
}
__device__ __forceinline__ void mbar_init(uint32_t bar, uint32_t cnt) {
    asm volatile("mbarrier.init.shared.b64 [%0], %1;" :: "r"(bar), "r"(cnt) : "memory");
}
__device__ __forceinline__ void mbar_arrive_expect(uint32_t bar, uint32_t bytes) {
    asm volatile("mbarrier.arrive.expect_tx.shared.b64 _, [%0], %1;"
                 :: "r"(bar), "r"(bytes) : "memory");
}
__device__ __forceinline__ void bulk_g2s(uint32_t dst, const void* src,
                                         uint32_t bytes, uint32_t bar) {
    asm volatile(
        "cp.async.bulk.shared::cluster.global.mbarrier::complete_tx::bytes "
        "[%0], [%1], %2, [%3];"
        :: "r"(dst), "l"(src), "r"(bytes), "r"(bar) : "memory");
}
__device__ __forceinline__ void mbar_wait(uint32_t bar, uint32_t parity) {
    asm volatile(
        "{\n\t"
        ".reg .pred P;\n\t"
        "WL_%=:\n\t"
        "mbarrier.try_wait.parity.acquire.cta.shared::cta.b64 P, [%0], %1, 0x989680;\n\t"
        "@P bra WD_%=;\n\t"
        "bra WL_%=;\n\t"
        "WD_%=:\n\t"
        "}"
        :: "r"(bar), "r"(parity) : "memory");
}

// ---------------- tf32 helpers -------------------------------------------------
__device__ __forceinline__ uint32_t tf32u(float x) {
    uint32_t u;
    asm("cvt.rna.tf32.f32 %0, %1;" : "=r"(u) : "f"(x));
    return u;
}
__device__ __forceinline__ float tf32f(float x) {
    return __uint_as_float(tf32u(x));
}
__device__ __forceinline__ void mma8(float* d, const uint32_t* a,
                                     uint32_t b0, uint32_t b1) {
    asm("mma.sync.aligned.m16n8k8.row.col.f32.tf32.tf32.f32 "
        "{%0,%1,%2,%3}, {%4,%5,%6,%7}, {%8,%9}, {%0,%1,%2,%3};"
        : "+f"(d[0]), "+f"(d[1]), "+f"(d[2]), "+f"(d[3])
        : "r"(a[0]), "r"(a[1]), "r"(a[2]), "r"(a[3]), "r"(b0), "r"(b1));
}

// ============================================================================
// Transposes (unchanged)
// ============================================================================
__global__ __launch_bounds__(256) void transpose_x(const float* __restrict__ x) {
    __shared__ float t[32][33];
    const int bx = blockIdx.x * 32, by = blockIdx.y * 32;
    const int txx = threadIdx.x, tyy = threadIdx.y;
#pragma unroll
    for (int i = tyy; i < 32; i += 8)
        t[i][txx] = x[(size_t)(by + i) * IN_FEAT + bx + txx];
    __syncthreads();
#pragma unroll
    for (int i = tyy; i < 32; i += 8)
        g_xT[(size_t)(bx + i) * N_NODES + by + txx] = t[txx][i];
}

__global__ __launch_bounds__(256) void transpose_w(const float* __restrict__ WQ,
                                                   const float* __restrict__ WK,
                                                   const float* __restrict__ WV) {
    const float* W = (blockIdx.z == 0) ? WQ : ((blockIdx.z == 1) ? WK : WV);
    __shared__ float t[32][33];
    const int bx = blockIdx.x * 32, by = blockIdx.y * 32;
    const int txx = threadIdx.x, tyy = threadIdx.y;
#pragma unroll
    for (int i = tyy; i < 32; i += 8)
        t[i][txx] = W[(size_t)(by + i) * IN_FEAT + bx + txx];
    __syncthreads();
#pragma unroll
    for (int i = tyy; i < 32; i += 8)
        g_WT[(size_t)(bx + i) * E3 + blockIdx.z * 512 + by + txx] = t[txx][i];
}

// ============================================================================
// adj -> bitmask  [word][q]
// ============================================================================
__global__ __launch_bounds__(256) void adj_to_bits(const int* __restrict__ adj) {
    const int q    = blockIdx.x * 8 + (threadIdx.x >> 5);
    const int lane = threadIdx.x & 31;
    const int* row = adj + (size_t)q * N_NODES;
#pragma unroll 4
    for (int w = 0; w < 128; w++) {
        unsigned m = __ballot_sync(0xffffffffu, row[w * 32 + lane] > 0);
        if (lane == 0) g_adjbits[w * N_NODES + q] = m;
    }
}

// ============================================================================
// QKV GEMM (fp32-exact) — unchanged from R5 (head-major Q/K, node-major V)
// ============================================================================
#define QKV_KT 64
#define QKV_SMEM (4 * QKV_KT * 128 * 4)

__device__ __forceinline__ void qkv_issue(int t, int m0, int n0, int tid,
                                          float* As, float* Bs,
                                          uint32_t bar0, uint32_t bar1) {
    if (tid < 128) {
        const int buf = t & 1;
        const uint32_t bar = buf ? bar1 : bar0;
        mbar_arrive_expect(bar, 512);
        const int row = tid & 63;
        const int k   = t * QKV_KT + row;
        if (tid < 64) {
            bulk_g2s(smem_u32(&As[buf * QKV_KT * 128 + row * 128]),
                     &g_xT[(size_t)k * N_NODES + m0], 512, bar);
        } else {
            bulk_g2s(smem_u32(&Bs[buf * QKV_KT * 128 + row * 128]),
                     &g_WT[(size_t)k * E3 + n0], 512, bar);
        }
    }
}

__global__ __launch_bounds__(512, 1) void qkv_gemm() {
    extern __shared__ float smem[];
    float* As = smem;
    float* Bs = smem + 2 * QKV_KT * 128;
    __shared__ __align__(8) unsigned long long mbar[2];

    const int tid = threadIdx.x;
    const int tx  = tid & 31;
    const int ty  = tid >> 5;
    const int n0  = blockIdx.x * 128;
    const int m0  = blockIdx.y * 128;
    const uint32_t bar0 = smem_u32(&mbar[0]);
    const uint32_t bar1 = smem_u32(&mbar[1]);

    if (blockIdx.x == 0 && blockIdx.y == 0 && tid == 0) g_fixcount = 0;

    if (tid == 0) { mbar_init(bar0, 128); mbar_init(bar1, 128); }
    __syncthreads();

    qkv_issue(0, m0, n0, tid, As, Bs, bar0, bar1);
    qkv_issue(1, m0, n0, tid, As, Bs, bar0, bar1);

    unsigned long long c[4][4];
#pragma unroll
    for (int i = 0; i < 4; i++)
#pragma unroll
        for (int j = 0; j < 4; j++) c[i][j] = 0ULL;

    const int ntiles = IN_FEAT / QKV_KT;
    for (int t = 0; t < ntiles; t++) {
        const int buf = t & 1;
        mbar_wait(buf ? bar1 : bar0, (t >> 1) & 1);
        const float* a = As + buf * QKV_KT * 128;
        const float* b = Bs + buf * QKV_KT * 128;
#pragma unroll 8
        for (int k = 0; k < QKV_KT; k++) {
            const ulonglong2* ap = (const ulonglong2*)&a[k * 128 + ty * 8];
            ulonglong2 a01 = ap[0];
            ulonglong2 a23 = ap[1];
            float4 bv = *(const float4*)&b[k * 128 + tx * 4];
            unsigned long long bd[4];
            bd[0] = pack2(bv.x, bv.x);
            bd[1] = pack2(bv.y, bv.y);
            bd[2] = pack2(bv.z, bv.z);
            bd[3] = pack2(bv.w, bv.w);
#pragma unroll
            for (int j = 0; j < 4; j++) {
                c[0][j] = fma2(a01.x, bd[j], c[0][j]);
                c[1][j] = fma2(a01.y, bd[j], c[1][j]);
                c[2][j] = fma2(a23.x, bd[j], c[2][j]);
                c[3][j] = fma2(a23.y, bd[j], c[3][j]);
            }
        }
        __syncthreads();
        if (t + 2 < ntiles) qkv_issue(t + 2, m0, n0, tid, As, Bs, bar0, bar1);
    }

    const int col = (n0 & 511) + tx * 4;
    float* pb;
    size_t rs;
    if (n0 < 512)       { pb = g_Qh + (size_t)(col >> 6) * (N_NODES * 64) + (col & 63); rs = 64; }
    else if (n0 < 1024) { pb = g_Kh + (size_t)(col >> 6) * (N_NODES * 64) + (col & 63); rs = 64; }
    else                { pb = g_V + col; rs = 512; }

#pragma unroll
    for (int mp = 0; mp < 4; mp++) {
        float lo0, hi0, lo1, hi1, lo2, hi2, lo3, hi3;
        unpack2(c[mp][0], lo0, hi0);
        unpack2(c[mp][1], lo1, hi1);
        unpack2(c[mp][2], lo2, hi2);
        unpack2(c[mp][3], lo3, hi3);
        const size_t row0 = m0 + ty * 8 + mp * 2;
        *(float4*)&pb[row0 * rs]       = make_float4(lo0, lo1, lo2, lo3);
        *(float4*)&pb[(row0 + 1) * rs] = make_float4(hi0, hi1, hi2, hi3);
    }
}

// ============================================================================
// K -> tf32-rounded, B-fragment-permuted tile images (64 keys x 64 d = 16 KB).
// Within a tile row r, element d lands at p(d) = (d&3)*16 + (d>>4)*4
//                                              + ((d>>3)&1)*2 + ((d>>2)&1).
// One block per (tile, head); 256 thr = 64 rows x 4 col-segments of 16.
// ============================================================================
__global__ __launch_bounds__(256) void convert_k_perm() {
    const int t  = blockIdx.x;
    const int h  = blockIdx.y;
    const int r  = threadIdx.x >> 2;
    const int cs = threadIdx.x & 3;

    const float* src = g_Kh + ((size_t)h * N_NODES + t * 64 + r) * 64 + cs * 16;
    float s[16];
#pragma unroll
    for (int j = 0; j < 4; j++) {
        float4 v = *(const float4*)&src[j * 4];
        s[j * 4 + 0] = tf32f(v.x);
        s[j * 4 + 1] = tf32f(v.y);
        s[j * 4 + 2] = tf32f(v.z);
        s[j * 4 + 3] = tf32f(v.w);
    }
    float* dst = g_Kp + ((size_t)(h * 64 + t)) * 4096 + r * 64 + cs * 4;
#pragma unroll
    for (int l4 = 0; l4 < 4; l4++)
        *(float4*)&dst[l4 * 16] = make_float4(s[l4], s[4 + l4], s[8 + l4], s[12 + l4]);
}

// ============================================================================
// Rare-path masked argmax update for one row (16 scores of this tile).
// ============================================================================
__device__ __forceinline__ void rare_update(const float (&acc)[8][4], int cofs,
                                            int q, int t, int l4,
                                            float& best, float& best2, int& bk) {
    const unsigned w0 = g_adjbits[(size_t)(2 * t) * N_NODES + q];
    const unsigned w1 = g_adjbits[(size_t)(2 * t + 1) * N_NODES + q];
    float mv[16];
#pragma unroll
    for (int nf = 0; nf < 8; nf++) {
        const unsigned wd = (nf < 4) ? w0 : w1;
        const int sh = (nf & 3) * 8 + l4 * 2;
        mv[nf * 2 + 0] = ((wd >> sh) & 1u)       ? acc[nf][cofs]     : -3e38f;
        mv[nf * 2 + 1] = ((wd >> (sh + 1)) & 1u) ? acc[nf][cofs + 1] : -3e38f;
    }
    float mmax = mv[0];
#pragma unroll
    for (int j = 1; j < 16; j++) mmax = fmaxf(mmax, mv[j]);

    if (mmax > best) {
        float sec = -3e38f;
        int   idx = bk;
        bool  taken = false;
#pragma unroll
        for (int j = 0; j < 16; j++) {
            if (mv[j] == mmax && !taken) {
                taken = true;
                idx = t * 64 + (j >> 1) * 8 + l4 * 2 + (j & 1);
            } else {
                sec = fmaxf(sec, mv[j]);
            }
        }
        best2 = fmaxf(best2, fmaxf(best, sec));
        best  = mmax;
        bk    = idx;
    } else if (mmax > best2) {
        best2 = mmax;
    }
}

// ============================================================================
// Score argmax via mma.sync tf32 + lazy masked epilogue.
// Block = 64 q rows x 1 head, 4 warps; K tiles arrive as single 16KB bulk
// copies of the pre-permuted images (double buffered).
// ============================================================================
__global__ __launch_bounds__(128, 4) void score_mma() {
    __shared__ float sK[2][4096];
    __shared__ __align__(8) unsigned long long s_bar[2];

    const int tid  = threadIdx.x;
    const int w    = tid >> 5;
    const int lane = tid & 31;
    const int g    = lane >> 2;
    const int l4   = lane & 3;
    const int h    = blockIdx.y;
    const int qt   = blockIdx.x;
    const int qA   = qt * 64 + w * 16 + g;
    const int qB   = qA + 8;

    const uint32_t bar0 = smem_u32(&s_bar[0]);
    const uint32_t bar1 = smem_u32(&s_bar[1]);
    const uint32_t sK0  = smem_u32(&sK[0][0]);
    const uint32_t sK1  = smem_u32(&sK[1][0]);
    const float* Ksrc   = g_Kp + (size_t)h * 64 * 4096;

    if (tid == 0) { mbar_init(bar0, 1); mbar_init(bar1, 1); }
    __syncthreads();

    if (tid == 0) {
        mbar_arrive_expect(bar0, 16384);
        bulk_g2s(sK0, Ksrc, 16384, bar0);
        mbar_arrive_expect(bar1, 16384);
        bulk_g2s(sK1, Ksrc + 4096, 16384, bar1);
    }

    // A fragments (tf32-rounded Q), register-resident
    uint32_t a[8][4];
    {
        const float* Qp  = g_Qh + ((size_t)h * N_NODES + qA) * 64;
        const float* Qp8 = Qp + 8 * 64;
#pragma unroll
        for (int s = 0; s < 8; s++) {
            a[s][0] = tf32u(Qp [s * 8 + l4]);
            a[s][1] = tf32u(Qp8[s * 8 + l4]);
            a[s][2] = tf32u(Qp [s * 8 + 4 + l4]);
            a[s][3] = tf32u(Qp8[s * 8 + 4 + l4]);
        }
    }

    float bestA = -3e38f, best2A = -3e38f;
    float bestB = -3e38f, best2B = -3e38f;
    int   bkA = 0, bkB = 0;

    for (int t = 0; t < 64; t++) {
        const int buf = t & 1;
        const int ph  = (t >> 1) & 1;
        mbar_wait(buf ? bar1 : bar0, ph);

        float acc[8][4];
#pragma unroll
        for (int nf = 0; nf < 8; nf++) {
            acc[nf][0] = 0.f; acc[nf][1] = 0.f;
            acc[nf][2] = 0.f; acc[nf][3] = 0.f;
        }
        const float* kb = &sK[buf][0];
#pragma unroll
        for (int nf = 0; nf < 8; nf++) {
            const float4* kp = (const float4*)&kb[(nf * 8 + g) * 64 + l4 * 16];
#pragma unroll
            for (int sp = 0; sp < 4; sp++) {
                const float4 b = kp[sp];
                mma8(acc[nf], a[2 * sp],     __float_as_uint(b.x), __float_as_uint(b.y));
                mma8(acc[nf], a[2 * sp + 1], __float_as_uint(b.z), __float_as_uint(b.w));
            }
        }
        __syncthreads();                  // all warps done reading sK[buf]
        if (tid == 0 && t + 2 < 64) {
            const uint32_t bar = buf ? bar1 : bar0;
            mbar_arrive_expect(bar, 16384);
            bulk_g2s(buf ? sK1 : sK0, Ksrc + (size_t)(t + 2) * 4096, 16384, bar);
        }

        // lazy epilogue: raw max trees, rare masked path
        float tA = fmaxf(acc[0][0], acc[0][1]);
        float tB = fmaxf(acc[0][2], acc[0][3]);
#pragma unroll
        for (int nf = 1; nf < 8; nf++) {
            tA = fmaxf(tA, fmaxf(acc[nf][0], acc[nf][1]));
            tB = fmaxf(tB, fmaxf(acc[nf][2], acc[nf][3]));
        }
        if (tA > best2A) rare_update(acc, 0, qA, t, l4, bestA, best2A, bkA);
        if (tB > best2B) rare_update(acc, 2, qB, t, l4, bestB, best2B, bkB);
    }

    // quad reduction (lanes sharing the same q rows)
#pragma unroll
    for (int off = 1; off < 4; off <<= 1) {
        float ob  = __shfl_xor_sync(0xffffffffu, bestA, off);
        int   obk = __shfl_xor_sync(0xffffffffu, bkA,  off);
        float ob2 = __shfl_xor_sync(0xffffffffu, best2A, off);
        best2A = fmaxf(fmaxf(best2A, ob2), fminf(bestA, ob));
        if (ob > bestA || (ob == bestA && obk < bkA)) { bestA = ob; bkA = obk; }

        ob  = __shfl_xor_sync(0xffffffffu, bestB, off);
        obk = __shfl_xor_sync(0xffffffffu, bkB,  off);
        ob2 = __shfl_xor_sync(0xffffffffu, best2B, off);
        best2B = fmaxf(fmaxf(best2B, ob2), fminf(bestB, ob));
        if (ob > bestB || (ob == bestB && obk < bkB)) { bestB = ob; bkB = obk; }
    }

    if (l4 == 0) {
        const int hqA = h * N_NODES + qA;
        const int hqB = h * N_NODES + qB;
        g_argmax[hqA] = bkA;
        g_argmax[hqB] = bkB;
        if (bestA - best2A < BAND) g_fixlist[atomicAdd(&g_fixcount, 1)] = hqA;
        if (bestB - best2B < BAND) g_fixlist[atomicAdd(&g_fixcount, 1)] = hqB;
    }
}

// ============================================================================
// Pass 2: exact fp32 re-argmax of flagged rows (block per row).
// ============================================================================
__global__ __launch_bounds__(256) void rescan() {
    __shared__ float s_best[8];
    __shared__ int   s_bk[8];
    const int nfix = g_fixcount;
    const int tid = threadIdx.x, lane = tid & 31, wrp = tid >> 5;

    for (int i = blockIdx.x; i < nfix; i += gridDim.x) {
        const int hq = g_fixlist[i];
        const int h = hq >> 12, q = hq & (N_NODES - 1);
        const float* Qr = g_Qh + ((size_t)h * N_NODES + q) * 64;
        float qv[64];
#pragma unroll
        for (int j = 0; j < 16; j++) {
            float4 v = *(const float4*)&Qr[j * 4];
            qv[j*4] = v.x; qv[j*4+1] = v.y; qv[j*4+2] = v.z; qv[j*4+3] = v.w;
        }

        float best = -3e38f;
        int   bk   = 1 << 30;
        for (int k = tid; k < N_NODES; k += 256) {
            const unsigned wd = g_adjbits[(k >> 5) * N_NODES + q];
            if ((wd >> (k & 31)) & 1u) {
                const float* Kr = g_Kh + ((size_t)h * N_NODES + k) * 64;
                float d = 0.f;
#pragma unroll
                for (int j = 0; j < 16; j++) {
                    float4 v = *(const float4*)&Kr[j * 4];
                    d += qv[j*4] * v.x + qv[j*4+1] * v.y
                       + qv[j*4+2] * v.z + qv[j*4+3] * v.w;
                }
                if (d > best || (d == best && k < bk)) { best = d; bk = k; }
            }
        }
#pragma unroll
        for (int off = 16; off > 0; off >>= 1) {
            float ob  = __shfl_xor_sync(0xffffffffu, best, off);
            int   obk = __shfl_xor_sync(0xffffffffu, bk, off);
            if (ob > best || (ob == best && obk < bk)) { best = ob; bk = obk; }
        }
        if (lane == 0) { s_best[wrp] = best; s_bk[wrp] = bk; }
        __syncthreads();
        if (tid == 0) {
            float b = s_best[0]; int k = s_bk[0];
#pragma unroll
            for (int j = 1; j < 8; j++)
                if (s_best[j] > b || (s_best[j] == b && s_bk[j] < k)) {
                    b = s_best[j]; k = s_bk[j];
                }
            g_argmax[hq] = k;
        }
        __syncthreads();
    }
}

// ============================================================================
// out[q, h*64+d] = V[argmax(h,q), h*64+d] / HEADS
// ============================================================================
__global__ __launch_bounds__(256) void gather_out(float* __restrict__ out) {
    const int idx = blockIdx.x * blockDim.x + threadIdx.x;
    const int q   = idx >> 7;
    const int c4  = idx & 127;
    const int h   = c4 >> 4;
    const int k   = g_argmax[h * N_NODES + q];
    float4 t = *(const float4*)&g_V[(size_t)k * 512 + c4 * 4];
    float4 v = make_float4(t.x * 0.125f, t.y * 0.125f, t.z * 0.125f, t.w * 0.125f);
    *(float4*)&out[(size_t)idx * 4] = v;
}

// ============================================================================
extern "C" void kernel_launch(void* const* d_in, const int* in_sizes, int n_in,
                              void* d_out, int out_size)
{
    const float* x   = (const float*)d_in[0];
    const int*   adj = (const int*)d_in[1];
    const float* WQ  = (const float*)d_in[2];
    const float* WK  = (const float*)d_in[3];
    const float* WV  = (const float*)d_in[4];
    float* out = (float*)d_out;

    cudaFuncSetAttribute(qkv_gemm,
                         cudaFuncAttributeMaxDynamicSharedMemorySize, QKV_SMEM);

    dim3 tb(32, 8);
    transpose_x<<<dim3(IN_FEAT / 32, N_NODES / 32), tb>>>(x);
    transpose_w<<<dim3(IN_FEAT / 32, 512 / 32, 3), tb>>>(WQ, WK, WV);
    adj_to_bits<<<N_NODES / 8, 256>>>(adj);

    qkv_gemm<<<dim3(E3 / 128, N_NODES / 128), 512, QKV_SMEM>>>();

    convert_k_perm<<<dim3(64, HEADS), 256>>>();

    score_mma<<<dim3(N_NODES / 64, HEADS), 128>>>();

    rescan<<<2048, 256>>>();

    gather_out<<<(N_NODES * 512 / 4) / 256, 256>>>(out);
}

// round 7
// speedup vs baseline: 1.4974x; 1.4974x over previous
#include <cuda_runtime.h>
#include <cuda_fp16.h>
#include <cstdint>

#define N_NODES 4096
#define IN_FEAT 512
#define E3      1536
#define HEADS   8
#define HEAD_DIM 64
#define BAND    0.075f

// ---------------- scratch (static device globals: no allocation) ------------
__device__ float    g_xT[IN_FEAT * N_NODES];     // [k][m]
__device__ float    g_WT[IN_FEAT * E3];          // [k][n]
__device__ float    g_Qh[HEADS * N_NODES * 64];  // head-major [h][node][d]
__device__ float    g_Kh[HEADS * N_NODES * 64];
__device__ __half   g_Kp16[HEADS * 64 * 4096];   // per-(h,tile) fragment-ordered fp16
__device__ float    g_V[N_NODES * 512];          // node-major
__device__ unsigned g_adjbits[128 * N_NODES];    // [word][q]
__device__ int      g_argmax[HEADS * N_NODES];
__device__ int      g_fixcount;
__device__ int      g_fixlist[HEADS * N_NODES];

// ---------------- packed fp32x2 helpers (qkv gemm) ---------------------------
__device__ __forceinline__ unsigned long long pack2(float lo, float hi) {
    unsigned long long r;
    asm("mov.b64 %0, {%1, %2};" : "=l"(r) : "f"(lo), "f"(hi));
    return r;
}
__device__ __forceinline__ void unpack2(unsigned long long v, float& lo, float& hi) {
    asm("mov.b64 {%0, %1}, %2;" : "=f"(lo), "=f"(hi) : "l"(v));
}
__device__ __forceinline__ unsigned long long fma2(unsigned long long a,
                                                   unsigned long long b,
                                                   unsigned long long c) {
    unsigned long long d;
    asm("fma.rn.f32x2 %0, %1, %2, %3;" : "=l"(d) : "l"(a), "l"(b), "l"(c));
    return d;
}

// ---------------- mbarrier + bulk-copy helpers --------------------------------
__device__ __forceinline__ uint32_t smem_u32(const void* p) {
    uint32_t a;
    asm("{ .reg .u64 t; cvta.to.shared.u64 t, %1; cvt.u32.u64 %0, t; }"
        : "=r"(a) : "l"(p));
    return a;
}
__device__ __forceinline__ void mbar_init(uint32_t bar, uint32_t cnt) {
    asm volatile("mbarrier.init.shared.b64 [%0], %1;" :: "r"(bar), "r"(cnt) : "memory");
}
__device__ __forceinline__ void mbar_arrive_expect(uint32_t bar, uint32_t bytes) {
    asm volatile("mbarrier.arrive.expect_tx.shared.b64 _, [%0], %1;"
                 :: "r"(bar), "r"(bytes) : "memory");
}
__device__ __forceinline__ void bulk_g2s(uint32_t dst, const void* src,
                                         uint32_t bytes, uint32_t bar) {
    asm volatile(
        "cp.async.bulk.shared::cluster.global.mbarrier::complete_tx::bytes "
        "[%0], [%1], %2, [%3];"
        :: "r"(dst), "l"(src), "r"(bytes), "r"(bar) : "memory");
}
__device__ __forceinline__ void mbar_wait(uint32_t bar, uint32_t parity) {
    asm volatile(
        "{\n\t"
        ".reg .pred P;\n\t"
        "WL_%=:\n\t"
        "mbarrier.try_wait.parity.acquire.cta.shared::cta.b64 P, [%0], %1, 0x989680;\n\t"
        "@P bra WD_%=;\n\t"
        "bra WL_%=;\n\t"
        "WD_%=:\n\t"
        "}"
        :: "r"(bar), "r"(parity) : "memory");
}

// ---------------- fp16 MMA helpers --------------------------------------------
__device__ __forceinline__ uint32_t pack_h2(float x, float y) {
    __half2 v = __floats2half2_rn(x, y);
    return *reinterpret_cast<uint32_t*>(&v);
}
__device__ __forceinline__ void mma16(float* d, const uint32_t* a,
                                      uint32_t b0, uint32_t b1) {
    asm("mma.sync.aligned.m16n8k16.row.col.f32.f16.f16.f32 "
        "{%0,%1,%2,%3}, {%4,%5,%6,%7}, {%8,%9}, {%0,%1,%2,%3};"
        : "+f"(d[0]), "+f"(d[1]), "+f"(d[2]), "+f"(d[3])
        : "r"(a[0]), "r"(a[1]), "r"(a[2]), "r"(a[3]), "r"(b0), "r"(b1));
}

// ============================================================================
// Transposes (unchanged)
// ============================================================================
__global__ __launch_bounds__(256) void transpose_x(const float* __restrict__ x) {
    __shared__ float t[32][33];
    const int bx = blockIdx.x * 32, by = blockIdx.y * 32;
    const int txx = threadIdx.x, tyy = threadIdx.y;
#pragma unroll
    for (int i = tyy; i < 32; i += 8)
        t[i][txx] = x[(size_t)(by + i) * IN_FEAT + bx + txx];
    __syncthreads();
#pragma unroll
    for (int i = tyy; i < 32; i += 8)
        g_xT[(size_t)(bx + i) * N_NODES + by + txx] = t[txx][i];
}

__global__ __launch_bounds__(256) void transpose_w(const float* __restrict__ WQ,
                                                   const float* __restrict__ WK,
                                                   const float* __restrict__ WV) {
    const float* W = (blockIdx.z == 0) ? WQ : ((blockIdx.z == 1) ? WK : WV);
    __shared__ float t[32][33];
    const int bx = blockIdx.x * 32, by = blockIdx.y * 32;
    const int txx = threadIdx.x, tyy = threadIdx.y;
#pragma unroll
    for (int i = tyy; i < 32; i += 8)
        t[i][txx] = W[(size_t)(by + i) * IN_FEAT + bx + txx];
    __syncthreads();
#pragma unroll
    for (int i = tyy; i < 32; i += 8)
        g_WT[(size_t)(bx + i) * E3 + blockIdx.z * 512 + by + txx] = t[txx][i];
}

// ============================================================================
// adj -> bitmask  [word][q]
// ============================================================================
__global__ __launch_bounds__(256) void adj_to_bits(const int* __restrict__ adj) {
    const int q    = blockIdx.x * 8 + (threadIdx.x >> 5);
    const int lane = threadIdx.x & 31;
    const int* row = adj + (size_t)q * N_NODES;
#pragma unroll 4
    for (int w = 0; w < 128; w++) {
        unsigned m = __ballot_sync(0xffffffffu, row[w * 32 + lane] > 0);
        if (lane == 0) g_adjbits[w * N_NODES + q] = m;
    }
}

// ============================================================================
// QKV GEMM (fp32-exact) — unchanged (head-major Q/K, node-major V)
// ============================================================================
#define QKV_KT 64
#define QKV_SMEM (4 * QKV_KT * 128 * 4)

__device__ __forceinline__ void qkv_issue(int t, int m0, int n0, int tid,
                                          float* As, float* Bs,
                                          uint32_t bar0, uint32_t bar1) {
    if (tid < 128) {
        const int buf = t & 1;
        const uint32_t bar = buf ? bar1 : bar0;
        mbar_arrive_expect(bar, 512);
        const int row = tid & 63;
        const int k   = t * QKV_KT + row;
        if (tid < 64) {
            bulk_g2s(smem_u32(&As[buf * QKV_KT * 128 + row * 128]),
                     &g_xT[(size_t)k * N_NODES + m0], 512, bar);
        } else {
            bulk_g2s(smem_u32(&Bs[buf * QKV_KT * 128 + row * 128]),
                     &g_WT[(size_t)k * E3 + n0], 512, bar);
        }
    }
}

__global__ __launch_bounds__(512, 1) void qkv_gemm() {
    extern __shared__ float smem[];
    float* As = smem;
    float* Bs = smem + 2 * QKV_KT * 128;
    __shared__ __align__(8) unsigned long long mbar[2];

    const int tid = threadIdx.x;
    const int tx  = tid & 31;
    const int ty  = tid >> 5;
    const int n0  = blockIdx.x * 128;
    const int m0  = blockIdx.y * 128;
    const uint32_t bar0 = smem_u32(&mbar[0]);
    const uint32_t bar1 = smem_u32(&mbar[1]);

    if (blockIdx.x == 0 && blockIdx.y == 0 && tid == 0) g_fixcount = 0;

    if (tid == 0) { mbar_init(bar0, 128); mbar_init(bar1, 128); }
    __syncthreads();

    qkv_issue(0, m0, n0, tid, As, Bs, bar0, bar1);
    qkv_issue(1, m0, n0, tid, As, Bs, bar0, bar1);

    unsigned long long c[4][4];
#pragma unroll
    for (int i = 0; i < 4; i++)
#pragma unroll
        for (int j = 0; j < 4; j++) c[i][j] = 0ULL;

    const int ntiles = IN_FEAT / QKV_KT;
    for (int t = 0; t < ntiles; t++) {
        const int buf = t & 1;
        mbar_wait(buf ? bar1 : bar0, (t >> 1) & 1);
        const float* a = As + buf * QKV_KT * 128;
        const float* b = Bs + buf * QKV_KT * 128;
#pragma unroll 8
        for (int k = 0; k < QKV_KT; k++) {
            const ulonglong2* ap = (const ulonglong2*)&a[k * 128 + ty * 8];
            ulonglong2 a01 = ap[0];
            ulonglong2 a23 = ap[1];
            float4 bv = *(const float4*)&b[k * 128 + tx * 4];
            unsigned long long bd[4];
            bd[0] = pack2(bv.x, bv.x);
            bd[1] = pack2(bv.y, bv.y);
            bd[2] = pack2(bv.z, bv.z);
            bd[3] = pack2(bv.w, bv.w);
#pragma unroll
            for (int j = 0; j < 4; j++) {
                c[0][j] = fma2(a01.x, bd[j], c[0][j]);
                c[1][j] = fma2(a01.y, bd[j], c[1][j]);
                c[2][j] = fma2(a23.x, bd[j], c[2][j]);
                c[3][j] = fma2(a23.y, bd[j], c[3][j]);
            }
        }
        __syncthreads();
        if (t + 2 < ntiles) qkv_issue(t + 2, m0, n0, tid, As, Bs, bar0, bar1);
    }

    const int col = (n0 & 511) + tx * 4;
    float* pb;
    size_t rs;
    if (n0 < 512)       { pb = g_Qh + (size_t)(col >> 6) * (N_NODES * 64) + (col & 63); rs = 64; }
    else if (n0 < 1024) { pb = g_Kh + (size_t)(col >> 6) * (N_NODES * 64) + (col & 63); rs = 64; }
    else                { pb = g_V + col; rs = 512; }

#pragma unroll
    for (int mp = 0; mp < 4; mp++) {
        float lo0, hi0, lo1, hi1, lo2, hi2, lo3, hi3;
        unpack2(c[mp][0], lo0, hi0);
        unpack2(c[mp][1], lo1, hi1);
        unpack2(c[mp][2], lo2, hi2);
        unpack2(c[mp][3], lo3, hi3);
        const size_t row0 = m0 + ty * 8 + mp * 2;
        *(float4*)&pb[row0 * rs]       = make_float4(lo0, lo1, lo2, lo3);
        *(float4*)&pb[(row0 + 1) * rs] = make_float4(hi0, hi1, hi2, hi3);
    }
}

// ============================================================================
// K -> fp16 fragment-ordered tile images (8 KB per 64x64 tile).
// Item id = (nf*4+s)*32 + lane holds the 8 bytes lane needs for mma(nf, s):
// key = nf*8 + (lane>>2), k = s*16 + (lane&3)*2 -> {k,k+1} and {k+8,k+9}.
// ============================================================================
__global__ __launch_bounds__(256) void convert_k16() {
    const int t = blockIdx.x, h = blockIdx.y;
    const float* src = g_Kh + ((size_t)h * N_NODES + t * 64) * 64;
    __half2* dst = (__half2*)(g_Kp16 + ((size_t)(h * 64 + t)) * 4096);
#pragma unroll
    for (int it = 0; it < 4; it++) {
        const int id   = it * 256 + threadIdx.x;  // 0..1023
        const int lane = id & 31;
        const int s    = (id >> 5) & 3;
        const int nf   = id >> 7;
        const int key  = nf * 8 + (lane >> 2);
        const int kc   = s * 16 + (lane & 3) * 2;
        const float* p = src + key * 64 + kc;
        dst[id * 2]     = __floats2half2_rn(p[0], p[1]);
        dst[id * 2 + 1] = __floats2half2_rn(p[8], p[9]);
    }
}

// ============================================================================
// Score argmax via mma.sync m16n8k16.f16 (same 10-bit mantissa as tf32) with
// mask folded into accumulator init; 4-deep bulk-copy ring; max-tree epilogue
// with rare index recovery. Block = 64 q x 1 head, 4 warps.
// ============================================================================
__device__ __forceinline__ void rare2(const float (&acc)[8][4], int cofs,
                                      int t, int l4, float tmax,
                                      float& best, float& best2, int& bk) {
    float sec = -3e38f;
    int   idx = bk;
    bool  taken = false;
#pragma unroll
    for (int nf = 0; nf < 8; nf++)
#pragma unroll
        for (int c = 0; c < 2; c++) {
            const float v = acc[nf][cofs + c];
            if (v == tmax && !taken) {
                taken = true;
                idx = t * 64 + nf * 8 + l4 * 2 + c;
            } else {
                sec = fmaxf(sec, v);
            }
        }
    best2 = fmaxf(best2, fmaxf(best, sec));
    best  = tmax;
    bk    = idx;
}

__global__ __launch_bounds__(128, 4) void score_mma() {
    __shared__ __half sK[4][4096];               // 4 x 8 KB ring
    __shared__ __align__(8) unsigned long long s_bar[4];

    const int tid  = threadIdx.x;
    const int w    = tid >> 5;
    const int lane = tid & 31;
    const int g    = lane >> 2;
    const int l4   = lane & 3;
    const int h    = blockIdx.y;
    const int qt   = blockIdx.x;
    const int qA   = qt * 64 + w * 16 + g;
    const int qB   = qA + 8;

    uint32_t bar[4];
#pragma unroll
    for (int i = 0; i < 4; i++) bar[i] = smem_u32(&s_bar[i]);
    const __half* Ksrc = g_Kp16 + (size_t)h * 64 * 4096;

    if (tid == 0) {
#pragma unroll
        for (int i = 0; i < 4; i++) mbar_init(bar[i], 1);
    }
    __syncthreads();

    if (tid == 0) {
#pragma unroll
        for (int i = 0; i < 4; i++) {
            mbar_arrive_expect(bar[i], 8192);
            bulk_g2s(smem_u32(&sK[i][0]), Ksrc + (size_t)i * 4096, 8192, bar[i]);
        }
    }

    // A fragments (fp16 Q), register-resident: 4 k-steps x 4 regs
    uint32_t a[4][4];
    {
        const float* QA = g_Qh + ((size_t)h * N_NODES + qA) * 64;
        const float* QB = QA + 8 * 64;
#pragma unroll
        for (int s = 0; s < 4; s++) {
            const int c = s * 16 + 2 * l4;
            a[s][0] = pack_h2(QA[c],     QA[c + 1]);
            a[s][1] = pack_h2(QB[c],     QB[c + 1]);
            a[s][2] = pack_h2(QA[c + 8], QA[c + 9]);
            a[s][3] = pack_h2(QB[c + 8], QB[c + 9]);
        }
    }

    float bestA = -3.3e38f, best2A = -3.3e38f;
    float bestB = -3.3e38f, best2B = -3.3e38f;
    int   bkA = 0, bkB = 0;
    const unsigned* abq = g_adjbits;

    for (int t = 0; t < 64; t++) {
        const int buf = t & 3;
        const int ph  = (t >> 2) & 1;
        mbar_wait(bar[buf], ph);

        // mask -> accumulator init (0 allowed, -3e38 masked)
        const unsigned w0A = abq[(size_t)(2 * t)     * N_NODES + qA];
        const unsigned w1A = abq[(size_t)(2 * t + 1) * N_NODES + qA];
        const unsigned w0B = abq[(size_t)(2 * t)     * N_NODES + qB];
        const unsigned w1B = abq[(size_t)(2 * t + 1) * N_NODES + qB];

        float acc[8][4];
#pragma unroll
        for (int nf = 0; nf < 8; nf++) {
            const unsigned wdA = (nf < 4) ? w0A : w1A;
            const unsigned wdB = (nf < 4) ? w0B : w1B;
            const int sh = (nf & 3) * 8 + l4 * 2;
            acc[nf][0] = ((wdA >> sh) & 1u)       ? 0.0f : -3e38f;
            acc[nf][1] = ((wdA >> (sh + 1)) & 1u) ? 0.0f : -3e38f;
            acc[nf][2] = ((wdB >> sh) & 1u)       ? 0.0f : -3e38f;
            acc[nf][3] = ((wdB >> (sh + 1)) & 1u) ? 0.0f : -3e38f;
        }

        const __half* kb = &sK[buf][0];
#pragma unroll
        for (int nf = 0; nf < 8; nf++) {
#pragma unroll
            for (int s = 0; s < 4; s++) {
                const uint2 bb = *(const uint2*)&kb[(size_t)(((nf * 4 + s) * 32 + lane)) * 4];
                mma16(acc[nf], a[s], bb.x, bb.y);
            }
        }
        __syncthreads();                  // all warps done with sK[buf]
        if (tid == 0 && t + 4 < 64) {
            mbar_arrive_expect(bar[buf], 8192);
            bulk_g2s(smem_u32(&sK[buf][0]), Ksrc + (size_t)(t + 4) * 4096, 8192, bar[buf]);
        }

        // masked max trees (values already masked via acc init)
        float tA = fmaxf(acc[0][0], acc[0][1]);
        float tB = fmaxf(acc[0][2], acc[0][3]);
#pragma unroll
        for (int nf = 1; nf < 8; nf++) {
            tA = fmaxf(tA, fmaxf(acc[nf][0], acc[nf][1]));
            tB = fmaxf(tB, fmaxf(acc[nf][2], acc[nf][3]));
        }
        if (tA > bestA) rare2(acc, 0, t, l4, tA, bestA, best2A, bkA);
        else            best2A = fmaxf(best2A, tA);
        if (tB > bestB) rare2(acc, 2, t, l4, tB, bestB, best2B, bkB);
        else            best2B = fmaxf(best2B, tB);
    }

    // quad reduction (lanes sharing the same q rows)
#pragma unroll
    for (int off = 1; off < 4; off <<= 1) {
        float ob  = __shfl_xor_sync(0xffffffffu, bestA, off);
        int   obk = __shfl_xor_sync(0xffffffffu, bkA,  off);
        float ob2 = __shfl_xor_sync(0xffffffffu, best2A, off);
        best2A = fmaxf(fmaxf(best2A, ob2), fminf(bestA, ob));
        if (ob > bestA || (ob == bestA && obk < bkA)) { bestA = ob; bkA = obk; }

        ob  = __shfl_xor_sync(0xffffffffu, bestB, off);
        obk = __shfl_xor_sync(0xffffffffu, bkB,  off);
        ob2 = __shfl_xor_sync(0xffffffffu, best2B, off);
        best2B = fmaxf(fmaxf(best2B, ob2), fminf(bestB, ob));
        if (ob > bestB || (ob == bestB && obk < bkB)) { bestB = ob; bkB = obk; }
    }

    if (l4 == 0) {
        const int hqA = h * N_NODES + qA;
        const int hqB = h * N_NODES + qB;
        g_argmax[hqA] = bkA;
        g_argmax[hqB] = bkB;
        if (bestA - best2A < BAND) g_fixlist[atomicAdd(&g_fixcount, 1)] = hqA;
        if (bestB - best2B < BAND) g_fixlist[atomicAdd(&g_fixcount, 1)] = hqB;
    }
}

// ============================================================================
// Pass 2: exact fp32 re-argmax of flagged rows (block per row).
// ============================================================================
__global__ __launch_bounds__(256) void rescan() {
    __shared__ float s_best[8];
    __shared__ int   s_bk[8];
    const int nfix = g_fixcount;
    const int tid = threadIdx.x, lane = tid & 31, wrp = tid >> 5;

    for (int i = blockIdx.x; i < nfix; i += gridDim.x) {
        const int hq = g_fixlist[i];
        const int h = hq >> 12, q = hq & (N_NODES - 1);
        const float* Qr = g_Qh + ((size_t)h * N_NODES + q) * 64;
        float qv[64];
#pragma unroll
        for (int j = 0; j < 16; j++) {
            float4 v = *(const float4*)&Qr[j * 4];
            qv[j*4] = v.x; qv[j*4+1] = v.y; qv[j*4+2] = v.z; qv[j*4+3] = v.w;
        }

        float best = -3e38f;
        int   bk   = 1 << 30;
        for (int k = tid; k < N_NODES; k += 256) {
            const unsigned wd = g_adjbits[(k >> 5) * N_NODES + q];
            if ((wd >> (k & 31)) & 1u) {
                const float* Kr = g_Kh + ((size_t)h * N_NODES + k) * 64;
                float d = 0.f;
#pragma unroll
                for (int j = 0; j < 16; j++) {
                    float4 v = *(const float4*)&Kr[j * 4];
                    d += qv[j*4] * v.x + qv[j*4+1] * v.y
                       + qv[j*4+2] * v.z + qv[j*4+3] * v.w;
                }
                if (d > best || (d == best && k < bk)) { best = d; bk = k; }
            }
        }
#pragma unroll
        for (int off = 16; off > 0; off >>= 1) {
            float ob  = __shfl_xor_sync(0xffffffffu, best, off);
            int   obk = __shfl_xor_sync(0xffffffffu, bk, off);
            if (ob > best || (ob == best && obk < bk)) { best = ob; bk = obk; }
        }
        if (lane == 0) { s_best[wrp] = best; s_bk[wrp] = bk; }
        __syncthreads();
        if (tid == 0) {
            float b = s_best[0]; int k = s_bk[0];
#pragma unroll
            for (int j = 1; j < 8; j++)
                if (s_best[j] > b || (s_best[j] == b && s_bk[j] < k)) {
                    b = s_best[j]; k = s_bk[j];
                }
            g_argmax[hq] = k;
        }
        __syncthreads();
    }
}

// ============================================================================
// out[q, h*64+d] = V[argmax(h,q), h*64+d] / HEADS
// ============================================================================
__global__ __launch_bounds__(256) void gather_out(float* __restrict__ out) {
    const int idx = blockIdx.x * blockDim.x + threadIdx.x;
    const int q   = idx >> 7;
    const int c4  = idx & 127;
    const int h   = c4 >> 4;
    const int k   = g_argmax[h * N_NODES + q];
    float4 t = *(const float4*)&g_V[(size_t)k * 512 + c4 * 4];
    float4 v = make_float4(t.x * 0.125f, t.y * 0.125f, t.z * 0.125f, t.w * 0.125f);
    *(float4*)&out[(size_t)idx * 4] = v;
}

// ============================================================================
extern "C" void kernel_launch(void* const* d_in, const int* in_sizes, int n_in,
                              void* d_out, int out_size)
{
    const float* x   = (const float*)d_in[0];
    const int*   adj = (const int*)d_in[1];
    const float* WQ  = (const float*)d_in[2];
    const float* WK  = (const float*)d_in[3];
    const float* WV  = (const float*)d_in[4];
    float* out = (float*)d_out;

    cudaFuncSetAttribute(qkv_gemm,
                         cudaFuncAttributeMaxDynamicSharedMemorySize, QKV_SMEM);

    dim3 tb(32, 8);
    transpose_x<<<dim3(IN_FEAT / 32, N_NODES / 32), tb>>>(x);
    transpose_w<<<dim3(IN_FEAT / 32, 512 / 32, 3), tb>>>(WQ, WK, WV);
    adj_to_bits<<<N_NODES / 8, 256>>>(adj);

    qkv_gemm<<<dim3(E3 / 128, N_NODES / 128), 512, QKV_SMEM>>>();

    convert_k16<<<dim3(64, HEADS), 256>>>();

    score_mma<<<dim3(N_NODES / 64, HEADS), 128>>>();

    rescan<<<2048, 256>>>();

    gather_out<<<(N_NODES * 512 / 4) / 256, 256>>>(out);
}